// round 10
// baseline (speedup 1.0000x reference)
#include <cuda_runtime.h>
#include <math.h>
#include <stdint.h>

// ---------------- problem constants ----------------
#define DDIM 512
#define TSTEPS 1024
#define BATCH 8
#define NSLOT 32
#define CPB 8             // CTAs per batch (plain grid)
#define SLICE 64          // d-slice per CTA
#define MROWS (BATCH*TSTEPS)
#define SCAN_THREADS 512
#define TPAD 516          // tape row stride (floats), 16B-aligned rows

// ---------------- static device scratch ----------------
__device__ float g_xproj[(size_t)MROWS * DDIM];
__device__ float g_siluz[(size_t)MROWS * DDIM];
__device__ float g_xw   [(size_t)MROWS * DDIM];
__device__ float g_hs   [(size_t)MROWS * DDIM];

// combined exchange: [0:64]=h_pre[t] slice, [64:128]=w_val[t-1] slice
__device__ __align__(16) float g_ex[BATCH][2][CPB][128];
__device__ int   g_flag[BATCH][CPB][32];   // use [b][c][0]; 128B padded

__device__ __forceinline__ float siluf(float v) { return v / (1.0f + __expf(-v)); }

__device__ __forceinline__ int ld_acquire_gpu(const int* p) {
    int v;
    asm volatile("ld.acquire.gpu.global.s32 %0, [%1];" : "=r"(v) : "l"(p) : "memory");
    return v;
}
__device__ __forceinline__ void st_release_gpu(int* p, int v) {
    asm volatile("st.release.gpu.global.s32 [%0], %1;" :: "l"(p), "r"(v) : "memory");
}

// ---------------- exact 1.5-entmax over 32 values, one per lane (proven) ----------------
__device__ __forceinline__ float entmax15_warp(float z, int lane) {
    const unsigned F = 0xffffffffu;
    float x0 = 0.5f * z;
    int rank = 0;
#pragma unroll
    for (int j = 0; j < 32; j++) {
        float xj = __shfl_sync(F, x0, j);
        rank += (xj > x0 || (xj == x0 && j < lane)) ? 1 : 0;
    }
    float m = x0;
#pragma unroll
    for (int o = 16; o > 0; o >>= 1) m = fmaxf(m, __shfl_xor_sync(F, m, o));
    float x = x0 - m;
    float s = 0.f, s2 = 0.f, zsv = 0.f;
#pragma unroll
    for (int j = 0; j < 32; j++) {
        float xj = __shfl_sync(F, x, j);
        int   rj = __shfl_sync(F, rank, j);
        if (rj <= lane) { s += xj; s2 += xj * xj; }
        if (rj == lane) zsv = xj;
    }
    float k1     = (float)(lane + 1);
    float mean   = s / k1;
    float meansq = s2 / k1;
    float ss     = k1 * (meansq - mean * mean);
    float delta  = (1.0f - ss) / k1;
    float tau    = mean - sqrtf(fmaxf(delta, 0.0f));
    unsigned bal = __ballot_sync(F, tau <= zsv);
    int support  = __popc(bal) - 1;
    float tau_star = __shfl_sync(F, tau, support);
    float p = fmaxf(x - tau_star, 0.0f);
    return p * p;
}

// ---------------- SGEMM: C[M,N] = A[M,K] @ B[N,K]^T (proven) ----------------
template <int MODE>
__global__ void __launch_bounds__(256)
sgemm(const float* __restrict__ Aext, const float* __restrict__ Bmat,
      float* __restrict__ Cout, int M, int N, int K)
{
    __shared__ float As[8 * 128];
    __shared__ float Bs[8 * 128];

    const int tid = threadIdx.x;
    const int bm = blockIdx.y * 128;
    const int bn = blockIdx.x * 128;
    const int lrow = tid >> 1;
    const int lk   = (tid & 1) * 4;
    const int tx = tid & 15;
    const int ty = tid >> 4;

    const float* A = (MODE == 0) ? Aext : ((MODE == 1) ? g_xproj : g_hs);

    float acc[8][8];
#pragma unroll
    for (int i = 0; i < 8; i++)
#pragma unroll
        for (int j = 0; j < 8; j++) acc[i][j] = 0.0f;

    for (int kt = 0; kt < K; kt += 8) {
        float4 av = *(const float4*)(A + (size_t)(bm + lrow) * K + kt + lk);
        if (MODE == 2) {
            float4 sv = *(const float4*)(g_siluz + (size_t)(bm + lrow) * K + kt + lk);
            av.x *= sv.x; av.y *= sv.y; av.z *= sv.z; av.w *= sv.w;
        }
        As[(lk + 0) * 128 + lrow] = av.x;
        As[(lk + 1) * 128 + lrow] = av.y;
        As[(lk + 2) * 128 + lrow] = av.z;
        As[(lk + 3) * 128 + lrow] = av.w;
        float4 bv = *(const float4*)(Bmat + (size_t)(bn + lrow) * K + kt + lk);
        Bs[(lk + 0) * 128 + lrow] = bv.x;
        Bs[(lk + 1) * 128 + lrow] = bv.y;
        Bs[(lk + 2) * 128 + lrow] = bv.z;
        Bs[(lk + 3) * 128 + lrow] = bv.w;
        __syncthreads();
#pragma unroll
        for (int kk = 0; kk < 8; kk++) {
            float af[8], bf[8];
            *(float4*)(af + 0) = *(const float4*)(As + kk * 128 + ty * 8 + 0);
            *(float4*)(af + 4) = *(const float4*)(As + kk * 128 + ty * 8 + 4);
            *(float4*)(bf + 0) = *(const float4*)(Bs + kk * 128 + tx * 8 + 0);
            *(float4*)(bf + 4) = *(const float4*)(Bs + kk * 128 + tx * 8 + 4);
#pragma unroll
            for (int i = 0; i < 8; i++)
#pragma unroll
                for (int j = 0; j < 8; j++)
                    acc[i][j] = fmaf(af[i], bf[j], acc[i][j]);
        }
        __syncthreads();
    }

#pragma unroll
    for (int i = 0; i < 8; i++) {
        const size_t m = (size_t)(bm + ty * 8 + i);
#pragma unroll
        for (int j = 0; j < 8; j++) {
            const int gn = bn + tx * 8 + j;
            float v = acc[i][j];
            if (MODE == 0) {
                if (gn < DDIM) g_xproj[m * DDIM + gn] = siluf(v);
                else           g_siluz[m * DDIM + (gn - DDIM)] = siluf(v);
            } else if (MODE == 1) {
                g_xw[m * DDIM + gn] = v;
            } else {
                Cout[m * DDIM + gn] = v;
            }
        }
    }
}

// ---------------- init: zero flags (every replay) ----------------
__global__ void init_kernel() {
    int i = blockIdx.x * blockDim.x + threadIdx.x;
    if (i < BATCH * CPB * 32) ((int*)g_flag)[i] = 0;
}

// ---------------- smem layout (float offsets; all 16B-aligned) ----------------
#define WH_F    0                       // 64*512 = 32768
#define TAPE_F  (WH_F + SLICE*DDIM)     // 32*516 = 16512
#define HPRE_F  (TAPE_F + NSLOT*TPAD)   // 512
#define HNEW_F  (HPRE_F + DDIM)         // 512
#define WVAL_F  (HNEW_F + DDIM)         // 512
#define RS_F    (WVAL_F + DDIM)         // 32
#define WS_F    (RS_F + 32)             // 32
#define AS_F    (WS_F + 32)             // 32
#define BVS_F   (AS_F + 32)             // 32
#define PUB_F   (BVS_F + 32)            // 128
#define BH_F    (PUB_F + 128)           // 64
#define XWB_F   (BH_F + 64)             // 64
#define SCAN_SMEM_F (XWB_F + 64)

// ---------------- dual-memory scan ----------------
__global__ void __launch_bounds__(SCAN_THREADS, 1)
scan_kernel(const float* __restrict__ W_h, const float* __restrict__ W_write,
            const float* __restrict__ b_h, float* __restrict__ dout)
{
    extern __shared__ float sm[];
    float* Wh_s   = sm + WH_F;
    float* tape_s = sm + TAPE_F;
    float* hpre_s = sm + HPRE_F;
    float* hnew_s = sm + HNEW_F;
    float* wval_s = sm + WVAL_F;
    float* rs_s   = sm + RS_F;
    float* ws_s   = sm + WS_F;
    float* a_s    = sm + AS_F;
    float* bv_s   = sm + BVS_F;
    float* pub_s  = sm + PUB_F;
    float* bh_s   = sm + BH_F;
    float* xwb_s  = sm + XWB_F;

    const int tid  = threadIdx.x;
    const int wid  = tid >> 5;
    const int lane = tid & 31;
    const int b    = blockIdx.x / CPB;
    const int c    = blockIdx.x % CPB;
    const int dbase = c * SLICE;
    const float scale = 0.044194173824159216f;  // 1/sqrt(512)
    const unsigned F = 0xffffffffu;

    // ---- weight shards ----
    for (int i = tid; i < SLICE * DDIM / 4; i += SCAN_THREADS)
        ((float4*)Wh_s)[i] = ((const float4*)(W_h + (size_t)dbase * DDIM))[i];

    // W_write rows (dbase + wid*4 + 0..3) in registers as float4 per k-chunk
    float4 ww4[4][4];
#pragma unroll
    for (int r = 0; r < 4; r++)
#pragma unroll
        for (int k = 0; k < 4; k++)
            ww4[r][k] = *(const float4*)(W_write +
                (size_t)(dbase + wid * 4 + r) * DDIM + lane * 4 + k * 128);

    for (int i = tid; i < NSLOT * TPAD; i += SCAN_THREADS) tape_s[i] = 0.0f;
    wval_s[tid] = 0.0f;
    hpre_s[tid] = g_xw[((size_t)b * TSTEPS) * DDIM + tid] + b_h[tid];
    if (tid < SLICE) {
        bh_s[tid]  = b_h[dbase + tid];
        xwb_s[tid] = g_xw[((size_t)b * TSTEPS + 1) * DDIM + dbase + tid];
    }
    if (tid < NSLOT) bv_s[tid] = 0.0f;
    __syncthreads();

    for (int t = 0; t < TSTEPS; t++) {
        const int par = t & 1;

        // ---- P0 (t>0): gather peers; copy own slice from pub_s ----
        if (t > 0) {
            if (wid == 0) {
                float4 v = ((const float4*)pub_s)[lane];
                int j = lane * 4;
                if (j < 64) *(float4*)&hpre_s[dbase + j]        = v;
                else        *(float4*)&wval_s[dbase + (j - 64)] = v;
            } else if (wid >= 8) {
                int p = wid - 8;
                if (p != c) {
                    if (lane == 0) {
                        while (ld_acquire_gpu(&g_flag[b][p][0]) < t) {}
                    }
                    __syncwarp();
                    float4 v = __ldcg((const float4*)&g_ex[b][par][p][lane * 4]);
                    int j = lane * 4;
                    if (j < 64) *(float4*)&hpre_s[p * 64 + j]        = v;
                    else        *(float4*)&wval_s[p * 64 + (j - 64)] = v;
                }
            }
        }
        __syncthreads();

        // ---- P1: fused deferred tape-update(t-1) + r-scores (float4) ----
        {
            const int n0 = 2 * wid;
            float bb0 = bv_s[n0];
            float bb1 = bv_s[n0 + 1];
            float4* t0 = (float4*)&tape_s[n0 * TPAD];
            float4* t1 = (float4*)&tape_s[(n0 + 1) * TPAD];
            const float4* wv4 = (const float4*)wval_s;
            const float4* hp4 = (const float4*)hpre_s;
            float r0 = 0.f, r1 = 0.f;
#pragma unroll
            for (int kk = 0; kk < 4; kk++) {
                int i = lane + kk * 32;
                float4 wv = wv4[i];
                float4 hp = hp4[i];
                float4 v0 = t0[i];
                float4 v1 = t1[i];
                v0.x = fmaf(bb0, wv.x - v0.x, v0.x); r0 = fmaf(v0.x, hp.x, r0);
                v0.y = fmaf(bb0, wv.y - v0.y, v0.y); r0 = fmaf(v0.y, hp.y, r0);
                v0.z = fmaf(bb0, wv.z - v0.z, v0.z); r0 = fmaf(v0.z, hp.z, r0);
                v0.w = fmaf(bb0, wv.w - v0.w, v0.w); r0 = fmaf(v0.w, hp.w, r0);
                v1.x = fmaf(bb1, wv.x - v1.x, v1.x); r1 = fmaf(v1.x, hp.x, r1);
                v1.y = fmaf(bb1, wv.y - v1.y, v1.y); r1 = fmaf(v1.y, hp.y, r1);
                v1.z = fmaf(bb1, wv.z - v1.z, v1.z); r1 = fmaf(v1.z, hp.z, r1);
                v1.w = fmaf(bb1, wv.w - v1.w, v1.w); r1 = fmaf(v1.w, hp.w, r1);
                t0[i] = v0;
                t1[i] = v1;
            }
#pragma unroll
            for (int o = 16; o > 0; o >>= 1) {
                r0 += __shfl_xor_sync(F, r0, o);
                r1 += __shfl_xor_sync(F, r1, o);
            }
            if (lane == 0) { rs_s[n0] = r0; rs_s[n0 + 1] = r1; }
        }
        __syncthreads();

        // ---- P2: entmax(a) on warp 0; side tasks on warps 4,6 ----
        if (wid == 0) {
            a_s[lane] = entmax15_warp(rs_s[lane] * scale, lane);
        } else if (t > 0) {
            if (wid == 4) {
                if (lane < 16 && t + 1 < TSTEPS)
                    ((float4*)xwb_s)[lane] = *(const float4*)
                        &g_xw[((size_t)b * TSTEPS + t + 1) * DDIM + dbase + lane * 4];
            } else if (wid == 6) {
                if (lane < 16)
                    *(float4*)&g_hs[((size_t)b * TSTEPS + (t - 1)) * DDIM + dbase + lane * 4] =
                        ((const float4*)&hnew_s[dbase])[lane];
            }
        }
        __syncthreads();

        // ---- P3: h_new[tid] = tanh(hpre + sum_n a_s[n]*tape[n][tid]) ----
        {
            float rd = 0.f;
#pragma unroll
            for (int n = 0; n < NSLOT; n++)
                rd = fmaf(a_s[n], tape_s[n * TPAD + tid], rd);
            hnew_s[tid] = tanhf(hpre_s[tid] + rd);
        }
        __syncthreads();

        // ---- P4: w-scores + w_val shard (float4); early-publish wval ----
        {
            const int n0 = 2 * wid;
            const float4* t0 = (const float4*)&tape_s[n0 * TPAD];
            const float4* t1 = (const float4*)&tape_s[(n0 + 1) * TPAD];
            const float4* hn4 = (const float4*)hnew_s;
            float s0 = 0.f, s1 = 0.f;
            float a0 = 0.f, a1 = 0.f, a2 = 0.f, a3 = 0.f;
#pragma unroll
            for (int kk = 0; kk < 4; kk++) {
                int i = lane + kk * 32;
                float4 hv = hn4[i];
                float4 v0 = t0[i];
                float4 v1 = t1[i];
                s0 = fmaf(v0.x, hv.x, s0); s0 = fmaf(v0.y, hv.y, s0);
                s0 = fmaf(v0.z, hv.z, s0); s0 = fmaf(v0.w, hv.w, s0);
                s1 = fmaf(v1.x, hv.x, s1); s1 = fmaf(v1.y, hv.y, s1);
                s1 = fmaf(v1.z, hv.z, s1); s1 = fmaf(v1.w, hv.w, s1);
                float4 w;
                w = ww4[0][kk];
                a0 = fmaf(w.x, hv.x, a0); a0 = fmaf(w.y, hv.y, a0);
                a0 = fmaf(w.z, hv.z, a0); a0 = fmaf(w.w, hv.w, a0);
                w = ww4[1][kk];
                a1 = fmaf(w.x, hv.x, a1); a1 = fmaf(w.y, hv.y, a1);
                a1 = fmaf(w.z, hv.z, a1); a1 = fmaf(w.w, hv.w, a1);
                w = ww4[2][kk];
                a2 = fmaf(w.x, hv.x, a2); a2 = fmaf(w.y, hv.y, a2);
                a2 = fmaf(w.z, hv.z, a2); a2 = fmaf(w.w, hv.w, a2);
                w = ww4[3][kk];
                a3 = fmaf(w.x, hv.x, a3); a3 = fmaf(w.y, hv.y, a3);
                a3 = fmaf(w.z, hv.z, a3); a3 = fmaf(w.w, hv.w, a3);
            }
#pragma unroll
            for (int o = 16; o > 0; o >>= 1) {
                s0 += __shfl_xor_sync(F, s0, o);
                s1 += __shfl_xor_sync(F, s1, o);
                a0 += __shfl_xor_sync(F, a0, o);
                a1 += __shfl_xor_sync(F, a1, o);
                a2 += __shfl_xor_sync(F, a2, o);
                a3 += __shfl_xor_sync(F, a3, o);
            }
            if (lane == 0) {
                ws_s[n0] = s0; ws_s[n0 + 1] = s1;
                *(float4*)&pub_s[64 + wid * 4] = make_float4(a0, a1, a2, a3);
                if (t + 1 < TSTEPS)
                    __stcg((float4*)&g_ex[b][(t + 1) & 1][c][64 + wid * 4],
                           make_float4(a0, a1, a2, a3));
            }
        }
        __syncthreads();

        // ---- P5: entmax(b) on warp 0; warps 1-15 W_h matvec (float4),
        //          early-publish hpre_next shard ----
        if (wid == 0) {
            bv_s[lane] = entmax15_warp(ws_s[lane] * scale, lane);
        } else if (t + 1 < TSTEPS) {
            const int r0 = (wid - 1) * 4;
            const bool has_extra = (wid <= 4);
            const int re = 60 + (wid - 1);
            const float4* w0 = (const float4*)&Wh_s[(r0 + 0) * DDIM];
            const float4* w1 = (const float4*)&Wh_s[(r0 + 1) * DDIM];
            const float4* w2 = (const float4*)&Wh_s[(r0 + 2) * DDIM];
            const float4* w3 = (const float4*)&Wh_s[(r0 + 3) * DDIM];
            const float4* we = (const float4*)&Wh_s[re * DDIM];
            const float4* hn4 = (const float4*)hnew_s;
            float a0 = 0.f, a1 = 0.f, a2 = 0.f, a3 = 0.f, ae = 0.f;
#pragma unroll
            for (int kk = 0; kk < 4; kk++) {
                int i = lane + kk * 32;
                float4 hv = hn4[i];
                float4 w;
                w = w0[i];
                a0 = fmaf(w.x, hv.x, a0); a0 = fmaf(w.y, hv.y, a0);
                a0 = fmaf(w.z, hv.z, a0); a0 = fmaf(w.w, hv.w, a0);
                w = w1[i];
                a1 = fmaf(w.x, hv.x, a1); a1 = fmaf(w.y, hv.y, a1);
                a1 = fmaf(w.z, hv.z, a1); a1 = fmaf(w.w, hv.w, a1);
                w = w2[i];
                a2 = fmaf(w.x, hv.x, a2); a2 = fmaf(w.y, hv.y, a2);
                a2 = fmaf(w.z, hv.z, a2); a2 = fmaf(w.w, hv.w, a2);
                w = w3[i];
                a3 = fmaf(w.x, hv.x, a3); a3 = fmaf(w.y, hv.y, a3);
                a3 = fmaf(w.z, hv.z, a3); a3 = fmaf(w.w, hv.w, a3);
                if (has_extra) {
                    w = we[i];
                    ae = fmaf(w.x, hv.x, ae); ae = fmaf(w.y, hv.y, ae);
                    ae = fmaf(w.z, hv.z, ae); ae = fmaf(w.w, hv.w, ae);
                }
            }
#pragma unroll
            for (int o = 16; o > 0; o >>= 1) {
                a0 += __shfl_xor_sync(F, a0, o);
                a1 += __shfl_xor_sync(F, a1, o);
                a2 += __shfl_xor_sync(F, a2, o);
                a3 += __shfl_xor_sync(F, a3, o);
                ae += __shfl_xor_sync(F, ae, o);
            }
            if (lane == 0) {
                float h0 = a0 + xwb_s[r0 + 0] + bh_s[r0 + 0];
                float h1 = a1 + xwb_s[r0 + 1] + bh_s[r0 + 1];
                float h2 = a2 + xwb_s[r0 + 2] + bh_s[r0 + 2];
                float h3 = a3 + xwb_s[r0 + 3] + bh_s[r0 + 3];
                *(float4*)&pub_s[r0] = make_float4(h0, h1, h2, h3);
                __stcg((float4*)&g_ex[b][(t + 1) & 1][c][r0],
                       make_float4(h0, h1, h2, h3));
                if (has_extra) {
                    float he = ae + xwb_s[re] + bh_s[re];
                    pub_s[re] = he;
                    __stcg(&g_ex[b][(t + 1) & 1][c][re], he);
                }
            }
        }
        __syncthreads();

        // ---- release flag for message t+1 (payload already stored) ----
        if (t + 1 < TSTEPS && tid == 0) {
            __threadfence();
            st_release_gpu(&g_flag[b][c][0], t + 1);
        }
    }

    // ---- post-loop: final deferred tape update (own cols), outputs ----
    const size_t TAPE_OFF = (size_t)BATCH * TSTEPS * DDIM;
    const size_t WORK_OFF = TAPE_OFF + (size_t)BATCH * NSLOT * DDIM;
    {
        const int n0 = 2 * wid;
        float bb0 = bv_s[n0];
        float bb1 = bv_s[n0 + 1];
#pragma unroll
        for (int h = 0; h < 2; h++) {
            int j = lane + h * 32;           // 0..63 own-column index
            int d = dbase + j;
            float wv = pub_s[64 + j];        // wval[T-1] own slice (local)
            float v0 = tape_s[n0 * TPAD + d];
            float v1 = tape_s[(n0 + 1) * TPAD + d];
            v0 = fmaf(bb0, wv - v0, v0);
            v1 = fmaf(bb1, wv - v1, v1);
            dout[TAPE_OFF + ((size_t)b * NSLOT + n0) * DDIM + d]     = v0;
            dout[TAPE_OFF + ((size_t)b * NSLOT + n0 + 1) * DDIM + d] = v1;
        }
    }
    if (tid < SLICE) {
        g_hs[((size_t)b * TSTEPS + TSTEPS - 1) * DDIM + dbase + tid] = hnew_s[dbase + tid];
        dout[WORK_OFF + (size_t)b * DDIM + dbase + tid] = hnew_s[dbase + tid];
    }
}

// ---------------- launcher ----------------
extern "C" void kernel_launch(void* const* d_in, const int* in_sizes, int n_in,
                              void* d_out, int out_size)
{
    const float* x       = (const float*)d_in[0];
    const float* W_in    = (const float*)d_in[1];
    const float* W_out   = (const float*)d_in[2];
    const float* W_h     = (const float*)d_in[3];
    const float* W_x     = (const float*)d_in[4];
    const float* b_h     = (const float*)d_in[5];
    const float* W_write = (const float*)d_in[6];
    float* out = (float*)d_out;

    const int scan_smem = SCAN_SMEM_F * (int)sizeof(float);
    cudaFuncSetAttribute(scan_kernel, cudaFuncAttributeMaxDynamicSharedMemorySize, scan_smem);

    dim3 blk(256);
    sgemm<0><<<dim3(1024 / 128, MROWS / 128), blk>>>(x, W_in, nullptr, MROWS, 1024, DDIM);
    sgemm<1><<<dim3(DDIM / 128, MROWS / 128), blk>>>(nullptr, W_x, nullptr, MROWS, DDIM, DDIM);
    init_kernel<<<8, 256>>>();
    scan_kernel<<<BATCH * CPB, SCAN_THREADS, scan_smem>>>(W_h, W_write, b_h, out);
    sgemm<2><<<dim3(DDIM / 128, MROWS / 128), blk>>>(nullptr, W_out, out, MROWS, DDIM, DDIM);
}

// round 11
// speedup vs baseline: 1.5120x; 1.5120x over previous
#include <cuda_runtime.h>
#include <math.h>
#include <stdint.h>

// ---------------- problem constants ----------------
#define DDIM 512
#define TSTEPS 1024
#define BATCH 8
#define NSLOT 32
#define CPB 8             // CTAs per batch (plain grid)
#define SLICE 64          // d-slice per CTA
#define MROWS (BATCH*TSTEPS)
#define SCAN_THREADS 512

// ---------------- static device scratch ----------------
__device__ float g_xproj[(size_t)MROWS * DDIM];
__device__ float g_siluz[(size_t)MROWS * DDIM];
__device__ float g_xw   [(size_t)MROWS * DDIM];
__device__ float g_hs   [(size_t)MROWS * DDIM];

// combined exchange: [0:64]=h_pre[t] slice, [64:128]=w_val[t-1] slice
__device__ __align__(16) float g_ex[BATCH][2][CPB][128];
__device__ int   g_flag[BATCH][CPB][32];   // use [b][c][0]; 128B padded

__device__ __forceinline__ float siluf(float v) { return v / (1.0f + __expf(-v)); }

__device__ __forceinline__ int ld_acquire_gpu(const int* p) {
    int v;
    asm volatile("ld.acquire.gpu.global.s32 %0, [%1];" : "=r"(v) : "l"(p) : "memory");
    return v;
}
__device__ __forceinline__ void st_release_gpu(int* p, int v) {
    asm volatile("st.release.gpu.global.s32 [%0], %1;" :: "l"(p), "r"(v) : "memory");
}

// ---------------- exact 1.5-entmax over 32 values, one per lane (proven) ----------------
__device__ __forceinline__ float entmax15_warp(float z, int lane) {
    const unsigned F = 0xffffffffu;
    float x0 = 0.5f * z;
    int rank = 0;
#pragma unroll
    for (int j = 0; j < 32; j++) {
        float xj = __shfl_sync(F, x0, j);
        rank += (xj > x0 || (xj == x0 && j < lane)) ? 1 : 0;
    }
    float m = x0;
#pragma unroll
    for (int o = 16; o > 0; o >>= 1) m = fmaxf(m, __shfl_xor_sync(F, m, o));
    float x = x0 - m;
    float s = 0.f, s2 = 0.f, zsv = 0.f;
#pragma unroll
    for (int j = 0; j < 32; j++) {
        float xj = __shfl_sync(F, x, j);
        int   rj = __shfl_sync(F, rank, j);
        if (rj <= lane) { s += xj; s2 += xj * xj; }
        if (rj == lane) zsv = xj;
    }
    float k1     = (float)(lane + 1);
    float mean   = s / k1;
    float meansq = s2 / k1;
    float ss     = k1 * (meansq - mean * mean);
    float delta  = (1.0f - ss) / k1;
    float tau    = mean - sqrtf(fmaxf(delta, 0.0f));
    unsigned bal = __ballot_sync(F, tau <= zsv);
    int support  = __popc(bal) - 1;
    float tau_star = __shfl_sync(F, tau, support);
    float p = fmaxf(x - tau_star, 0.0f);
    return p * p;
}

// ---------------- SGEMM: C[M,N] = A[M,K] @ B[N,K]^T (proven) ----------------
template <int MODE>
__global__ void __launch_bounds__(256)
sgemm(const float* __restrict__ Aext, const float* __restrict__ Bmat,
      float* __restrict__ Cout, int M, int N, int K)
{
    __shared__ float As[8 * 128];
    __shared__ float Bs[8 * 128];

    const int tid = threadIdx.x;
    const int bm = blockIdx.y * 128;
    const int bn = blockIdx.x * 128;
    const int lrow = tid >> 1;
    const int lk   = (tid & 1) * 4;
    const int tx = tid & 15;
    const int ty = tid >> 4;

    const float* A = (MODE == 0) ? Aext : ((MODE == 1) ? g_xproj : g_hs);

    float acc[8][8];
#pragma unroll
    for (int i = 0; i < 8; i++)
#pragma unroll
        for (int j = 0; j < 8; j++) acc[i][j] = 0.0f;

    for (int kt = 0; kt < K; kt += 8) {
        float4 av = *(const float4*)(A + (size_t)(bm + lrow) * K + kt + lk);
        if (MODE == 2) {
            float4 sv = *(const float4*)(g_siluz + (size_t)(bm + lrow) * K + kt + lk);
            av.x *= sv.x; av.y *= sv.y; av.z *= sv.z; av.w *= sv.w;
        }
        As[(lk + 0) * 128 + lrow] = av.x;
        As[(lk + 1) * 128 + lrow] = av.y;
        As[(lk + 2) * 128 + lrow] = av.z;
        As[(lk + 3) * 128 + lrow] = av.w;
        float4 bv = *(const float4*)(Bmat + (size_t)(bn + lrow) * K + kt + lk);
        Bs[(lk + 0) * 128 + lrow] = bv.x;
        Bs[(lk + 1) * 128 + lrow] = bv.y;
        Bs[(lk + 2) * 128 + lrow] = bv.z;
        Bs[(lk + 3) * 128 + lrow] = bv.w;
        __syncthreads();
#pragma unroll
        for (int kk = 0; kk < 8; kk++) {
            float af[8], bf[8];
            *(float4*)(af + 0) = *(const float4*)(As + kk * 128 + ty * 8 + 0);
            *(float4*)(af + 4) = *(const float4*)(As + kk * 128 + ty * 8 + 4);
            *(float4*)(bf + 0) = *(const float4*)(Bs + kk * 128 + tx * 8 + 0);
            *(float4*)(bf + 4) = *(const float4*)(Bs + kk * 128 + tx * 8 + 4);
#pragma unroll
            for (int i = 0; i < 8; i++)
#pragma unroll
                for (int j = 0; j < 8; j++)
                    acc[i][j] = fmaf(af[i], bf[j], acc[i][j]);
        }
        __syncthreads();
    }

#pragma unroll
    for (int i = 0; i < 8; i++) {
        const size_t m = (size_t)(bm + ty * 8 + i);
#pragma unroll
        for (int j = 0; j < 8; j++) {
            const int gn = bn + tx * 8 + j;
            float v = acc[i][j];
            if (MODE == 0) {
                if (gn < DDIM) g_xproj[m * DDIM + gn] = siluf(v);
                else           g_siluz[m * DDIM + (gn - DDIM)] = siluf(v);
            } else if (MODE == 1) {
                g_xw[m * DDIM + gn] = v;
            } else {
                Cout[m * DDIM + gn] = v;
            }
        }
    }
}

// ---------------- init: zero flags (every replay) ----------------
__global__ void init_kernel() {
    int i = blockIdx.x * blockDim.x + threadIdx.x;
    if (i < BATCH * CPB * 32) ((int*)g_flag)[i] = 0;
}

// ---------------- smem layout (float offsets) ----------------
#define WH_F    0                       // 64*512 = 32768
#define TAPE_F  (WH_F + SLICE*DDIM)     // 32*513 = 16416
#define HPRE_F  (TAPE_F + NSLOT*513)    // 512
#define HNEW_F  (HPRE_F + DDIM)         // 512
#define WVAL_F  (HNEW_F + DDIM)         // 512
#define RS_F    (WVAL_F + DDIM)         // 32
#define WS_F    (RS_F + 32)             // 32
#define AS_F    (WS_F + 32)             // 32
#define BVS_F   (AS_F + 32)             // 32
#define PUB_F   (BVS_F + 32)            // 128
#define BH_F    (PUB_F + 128)           // 64
#define XWB_F   (BH_F + 64)             // 64
#define SCAN_SMEM_F (XWB_F + 64)

// ---------------- dual-memory scan (R9 base + loop-bottom publish + P5 rebalance) ----------------
__global__ void __launch_bounds__(SCAN_THREADS, 1)
scan_kernel(const float* __restrict__ W_h, const float* __restrict__ W_write,
            const float* __restrict__ b_h, float* __restrict__ dout)
{
    extern __shared__ float sm[];
    float* Wh_s   = sm + WH_F;
    float* tape_s = sm + TAPE_F;
    float* hpre_s = sm + HPRE_F;
    float* hnew_s = sm + HNEW_F;
    float* wval_s = sm + WVAL_F;
    float* rs_s   = sm + RS_F;
    float* ws_s   = sm + WS_F;
    float* a_s    = sm + AS_F;
    float* bv_s   = sm + BVS_F;
    float* pub_s  = sm + PUB_F;
    float* bh_s   = sm + BH_F;
    float* xwb_s  = sm + XWB_F;

    const int tid  = threadIdx.x;
    const int wid  = tid >> 5;
    const int lane = tid & 31;
    const int b    = blockIdx.x / CPB;
    const int c    = blockIdx.x % CPB;
    const int dbase = c * SLICE;
    const float scale = 0.044194173824159216f;  // 1/sqrt(512)
    const unsigned F = 0xffffffffu;

    // ---- weight shards ----
    for (int i = tid; i < SLICE * DDIM / 4; i += SCAN_THREADS)
        ((float4*)Wh_s)[i] = ((const float4*)(W_h + (size_t)dbase * DDIM))[i];

    // W_write rows (dbase + wid*4 + 0..3) in registers
    float ww0[16], ww1[16], ww2[16], ww3[16];
    {
        const float* base = W_write + (size_t)(dbase + wid * 4) * DDIM + lane;
#pragma unroll
        for (int kk = 0; kk < 16; kk++) {
            ww0[kk] = base[kk * 32];
            ww1[kk] = base[DDIM + kk * 32];
            ww2[kk] = base[2 * DDIM + kk * 32];
            ww3[kk] = base[3 * DDIM + kk * 32];
        }
    }
    for (int i = tid; i < NSLOT * 513; i += SCAN_THREADS) tape_s[i] = 0.0f;
    wval_s[tid] = 0.0f;
    // full h_pre[0] = xw[0] + b_h  (work0 = 0)
    hpre_s[tid] = g_xw[((size_t)b * TSTEPS) * DDIM + tid] + b_h[tid];
    if (tid < SLICE) {
        bh_s[tid]  = b_h[dbase + tid];
        xwb_s[tid] = g_xw[((size_t)b * TSTEPS + 1) * DDIM + dbase + tid];
    }
    if (tid < NSLOT) bv_s[tid] = 0.0f;   // b[-1] = 0 -> first tape update no-op
    __syncthreads();

    for (int t = 0; t < TSTEPS; t++) {
        const int par = t & 1;

        // ---- P0 (t>0): gather peers (publish happened at prior loop bottom);
        //      side tasks on free warps ----
        if (t > 0) {
            if (wid >= 8) {
                int p = wid - 8;
                if (p != c) {
                    if (lane == 0) {
                        while (ld_acquire_gpu(&g_flag[b][p][0]) < t) {}
                    }
                    __syncwarp();
                    float4 v = __ldcg((const float4*)&g_ex[b][par][p][lane * 4]);
                    int j = lane * 4;
                    if (j < 64) *(float4*)&hpre_s[p * 64 + j]        = v;
                    else        *(float4*)&wval_s[p * 64 + (j - 64)] = v;
                }
            } else if (wid < 4) {
                int j = tid;                      // 0..127: copy own slice
                float v = pub_s[j];
                if (j < 64) hpre_s[dbase + j]        = v;
                else        wval_s[dbase + (j - 64)] = v;
            } else if (wid == 4 || wid == 5) {
                int j = tid - 128;                // prefetch xw[t+1] slice
                if (t + 1 < TSTEPS)
                    xwb_s[j] = g_xw[((size_t)b * TSTEPS + t + 1) * DDIM + dbase + j];
            } else {                              // wid 6,7: store h_new[t-1]
                int j = tid - 192;
                g_hs[((size_t)b * TSTEPS + (t - 1)) * DDIM + dbase + j] = hnew_s[dbase + j];
            }
        }
        __syncthreads();

        // ---- P1: fused deferred tape-update(t-1) + r-scores (warp w: rows 2w,2w+1) ----
        {
            const int n0 = 2 * wid;
            float bb0 = bv_s[n0];        // broadcast LDS
            float bb1 = bv_s[n0 + 1];
            float r0 = 0.f, r1 = 0.f;
            float* t0 = &tape_s[n0 * 513];
            float* t1 = t0 + 513;
#pragma unroll
            for (int kk = 0; kk < 16; kk++) {
                int d = lane + kk * 32;
                float wv = wval_s[d];
                float hp = hpre_s[d];
                float v0 = t0[d]; v0 = fmaf(bb0, wv - v0, v0); t0[d] = v0; r0 = fmaf(v0, hp, r0);
                float v1 = t1[d]; v1 = fmaf(bb1, wv - v1, v1); t1[d] = v1; r1 = fmaf(v1, hp, r1);
            }
#pragma unroll
            for (int o = 16; o > 0; o >>= 1) {
                r0 += __shfl_xor_sync(F, r0, o);
                r1 += __shfl_xor_sync(F, r1, o);
            }
            if (lane == 0) { rs_s[n0] = r0; rs_s[n0 + 1] = r1; }
        }
        __syncthreads();

        // ---- P2: entmax(a) on warp 0 ONLY -> a_s ----
        if (wid == 0) {
            float a = entmax15_warp(rs_s[lane] * scale, lane);
            a_s[lane] = a;
        }
        __syncthreads();

        // ---- P3: h_new[tid] = tanh(hpre + sum_n a_s[n]*tape[n][tid]) ----
        {
            float rd = 0.f;
#pragma unroll
            for (int n = 0; n < NSLOT; n++)
                rd = fmaf(a_s[n], tape_s[n * 513 + tid], rd);
            hnew_s[tid] = tanhf(hpre_s[tid] + rd);
        }
        __syncthreads();

        // ---- P4: w-scores (2 slots/warp) + w_val shard (4 rows/warp, regs) ----
        {
            const int n0 = 2 * wid;
            float s0 = 0.f, s1 = 0.f;
            float a0 = 0.f, a1 = 0.f, a2 = 0.f, a3 = 0.f;
            const float* t0 = &tape_s[n0 * 513];
            const float* t1 = t0 + 513;
#pragma unroll
            for (int kk = 0; kk < 16; kk++) {
                int d = lane + kk * 32;
                float hv = hnew_s[d];
                s0 = fmaf(t0[d], hv, s0);
                s1 = fmaf(t1[d], hv, s1);
                a0 = fmaf(ww0[kk], hv, a0);
                a1 = fmaf(ww1[kk], hv, a1);
                a2 = fmaf(ww2[kk], hv, a2);
                a3 = fmaf(ww3[kk], hv, a3);
            }
#pragma unroll
            for (int o = 16; o > 0; o >>= 1) {
                s0 += __shfl_xor_sync(F, s0, o);
                s1 += __shfl_xor_sync(F, s1, o);
                a0 += __shfl_xor_sync(F, a0, o);
                a1 += __shfl_xor_sync(F, a1, o);
                a2 += __shfl_xor_sync(F, a2, o);
                a3 += __shfl_xor_sync(F, a3, o);
            }
            if (lane == 0) {
                ws_s[n0] = s0; ws_s[n0 + 1] = s1;
                pub_s[64 + wid * 4 + 0] = a0;
                pub_s[64 + wid * 4 + 1] = a1;
                pub_s[64 + wid * 4 + 2] = a2;
                pub_s[64 + wid * 4 + 3] = a3;
            }
        }
        __syncthreads();

        // ---- P5: entmax(b) on warp 0 ONLY; warps 1-15 W_h matvec -> pub_s[0:64]
        //      (warps 12-15 take one extra row each: rows 60..63) ----
        if (wid == 0) {
            float bb = entmax15_warp(ws_s[lane] * scale, lane);
            bv_s[lane] = bb;
        } else if (t + 1 < TSTEPS) {
            const int r0 = (wid - 1) * 4;
            float a0 = 0.f, a1 = 0.f, a2 = 0.f, a3 = 0.f;
            const float* w0 = &Wh_s[(r0 + 0) * DDIM];
            const float* w1 = &Wh_s[(r0 + 1) * DDIM];
            const float* w2 = &Wh_s[(r0 + 2) * DDIM];
            const float* w3 = &Wh_s[(r0 + 3) * DDIM];
#pragma unroll
            for (int kk = 0; kk < 16; kk++) {
                int d = lane + kk * 32;
                float hv = hnew_s[d];
                a0 = fmaf(w0[d], hv, a0);
                a1 = fmaf(w1[d], hv, a1);
                a2 = fmaf(w2[d], hv, a2);
                a3 = fmaf(w3[d], hv, a3);
            }
#pragma unroll
            for (int o = 16; o > 0; o >>= 1) {
                a0 += __shfl_xor_sync(F, a0, o);
                a1 += __shfl_xor_sync(F, a1, o);
                a2 += __shfl_xor_sync(F, a2, o);
                a3 += __shfl_xor_sync(F, a3, o);
            }
            if (lane == 0) {
                pub_s[r0 + 0] = a0 + xwb_s[r0 + 0] + bh_s[r0 + 0];
                pub_s[r0 + 1] = a1 + xwb_s[r0 + 1] + bh_s[r0 + 1];
                pub_s[r0 + 2] = a2 + xwb_s[r0 + 2] + bh_s[r0 + 2];
                pub_s[r0 + 3] = a3 + xwb_s[r0 + 3] + bh_s[r0 + 3];
            }
            if (wid >= 12) {                  // extra row 60 + (wid-12)
                const int re = 60 + (wid - 12);
                const float* we = &Wh_s[re * DDIM];
                float ae = 0.f;
#pragma unroll
                for (int kk = 0; kk < 16; kk++) {
                    int d = lane + kk * 32;
                    ae = fmaf(we[d], hnew_s[d], ae);
                }
#pragma unroll
                for (int o = 16; o > 0; o >>= 1)
                    ae += __shfl_xor_sync(F, ae, o);
                if (lane == 0)
                    pub_s[re] = ae + xwb_s[re] + bh_s[re];
            }
        }
        __syncthreads();

        // ---- loop bottom: publish message t+1 (pub_s final) by warp c+8 ----
        if (t + 1 < TSTEPS && wid == c + 8) {
            float4 v = ((const float4*)pub_s)[lane];
            __stcg((float4*)&g_ex[b][(t + 1) & 1][c][lane * 4], v);
            __threadfence();
            __syncwarp();
            if (lane == 0) st_release_gpu(&g_flag[b][c][0], t + 1);
        }
    }

    // ---- post-loop: final deferred tape update (own cols), outputs ----
    const size_t TAPE_OFF = (size_t)BATCH * TSTEPS * DDIM;
    const size_t WORK_OFF = TAPE_OFF + (size_t)BATCH * NSLOT * DDIM;
    {
        const int n0 = 2 * wid;
        float bb0 = bv_s[n0];
        float bb1 = bv_s[n0 + 1];
#pragma unroll
        for (int h = 0; h < 2; h++) {
            int j = lane + h * 32;           // 0..63 own-column index
            int d = dbase + j;
            float wv = pub_s[64 + j];        // wval[T-1] own slice (local)
            float v0 = tape_s[n0 * 513 + d];
            float v1 = tape_s[(n0 + 1) * 513 + d];
            v0 = fmaf(bb0, wv - v0, v0);
            v1 = fmaf(bb1, wv - v1, v1);
            dout[TAPE_OFF + ((size_t)b * NSLOT + n0) * DDIM + d]     = v0;
            dout[TAPE_OFF + ((size_t)b * NSLOT + n0 + 1) * DDIM + d] = v1;
        }
    }
    if (tid < SLICE) {
        g_hs[((size_t)b * TSTEPS + TSTEPS - 1) * DDIM + dbase + tid] = hnew_s[dbase + tid];
        dout[WORK_OFF + (size_t)b * DDIM + dbase + tid] = hnew_s[dbase + tid];
    }
}

// ---------------- launcher ----------------
extern "C" void kernel_launch(void* const* d_in, const int* in_sizes, int n_in,
                              void* d_out, int out_size)
{
    const float* x       = (const float*)d_in[0];
    const float* W_in    = (const float*)d_in[1];
    const float* W_out   = (const float*)d_in[2];
    const float* W_h     = (const float*)d_in[3];
    const float* W_x     = (const float*)d_in[4];
    const float* b_h     = (const float*)d_in[5];
    const float* W_write = (const float*)d_in[6];
    float* out = (float*)d_out;

    const int scan_smem = SCAN_SMEM_F * (int)sizeof(float);
    cudaFuncSetAttribute(scan_kernel, cudaFuncAttributeMaxDynamicSharedMemorySize, scan_smem);

    dim3 blk(256);
    sgemm<0><<<dim3(1024 / 128, MROWS / 128), blk>>>(x, W_in, nullptr, MROWS, 1024, DDIM);
    sgemm<1><<<dim3(DDIM / 128, MROWS / 128), blk>>>(nullptr, W_x, nullptr, MROWS, DDIM, DDIM);
    init_kernel<<<8, 256>>>();
    scan_kernel<<<BATCH * CPB, SCAN_THREADS, scan_smem>>>(W_h, W_write, b_h, out);
    sgemm<2><<<dim3(DDIM / 128, MROWS / 128), blk>>>(nullptr, W_out, out, MROWS, DDIM, DDIM);
}

// round 12
// speedup vs baseline: 1.7573x; 1.1623x over previous
#include <cuda_runtime.h>
#include <math.h>
#include <stdint.h>

// ---------------- problem constants ----------------
#define DDIM 512
#define TSTEPS 1024
#define BATCH 8
#define NSLOT 32
#define CPB 8             // CTAs per batch (plain grid)
#define SLICE 64          // d-slice per CTA
#define MROWS (BATCH*TSTEPS)
#define SCAN_THREADS 512

// ---------------- static device scratch ----------------
__device__ float g_xproj[(size_t)MROWS * DDIM];
__device__ float g_siluz[(size_t)MROWS * DDIM];
__device__ float g_xw   [(size_t)MROWS * DDIM];
__device__ float g_hs   [(size_t)MROWS * DDIM];

// combined exchange: [0:64]=h_pre[t] slice, [64:128]=w_val[t-1] slice
__device__ __align__(16) float g_ex[BATCH][2][CPB][128];
__device__ int   g_flag[BATCH][CPB][32];   // use [b][c][0]; 128B padded

__device__ __forceinline__ float siluf(float v) { return v / (1.0f + __expf(-v)); }

__device__ __forceinline__ int ld_acquire_gpu(const int* p) {
    int v;
    asm volatile("ld.acquire.gpu.global.s32 %0, [%1];" : "=r"(v) : "l"(p) : "memory");
    return v;
}
__device__ __forceinline__ void st_release_gpu(int* p, int v) {
    asm volatile("st.release.gpu.global.s32 [%0], %1;" :: "l"(p), "r"(v) : "memory");
}

// ---------------- exact 1.5-entmax over 32 values, one per lane (proven) ----------------
__device__ __forceinline__ float entmax15_warp(float z, int lane) {
    const unsigned F = 0xffffffffu;
    float x0 = 0.5f * z;
    int rank = 0;
#pragma unroll
    for (int j = 0; j < 32; j++) {
        float xj = __shfl_sync(F, x0, j);
        rank += (xj > x0 || (xj == x0 && j < lane)) ? 1 : 0;
    }
    float m = x0;
#pragma unroll
    for (int o = 16; o > 0; o >>= 1) m = fmaxf(m, __shfl_xor_sync(F, m, o));
    float x = x0 - m;
    float s = 0.f, s2 = 0.f, zsv = 0.f;
#pragma unroll
    for (int j = 0; j < 32; j++) {
        float xj = __shfl_sync(F, x, j);
        int   rj = __shfl_sync(F, rank, j);
        if (rj <= lane) { s += xj; s2 += xj * xj; }
        if (rj == lane) zsv = xj;
    }
    float k1     = (float)(lane + 1);
    float mean   = s / k1;
    float meansq = s2 / k1;
    float ss     = k1 * (meansq - mean * mean);
    float delta  = (1.0f - ss) / k1;
    float tau    = mean - sqrtf(fmaxf(delta, 0.0f));
    unsigned bal = __ballot_sync(F, tau <= zsv);
    int support  = __popc(bal) - 1;
    float tau_star = __shfl_sync(F, tau, support);
    float p = fmaxf(x - tau_star, 0.0f);
    return p * p;
}

// ---------------- SGEMM: C[M,N] = A[M,K] @ B[N,K]^T (proven) ----------------
template <int MODE>
__global__ void __launch_bounds__(256)
sgemm(const float* __restrict__ Aext, const float* __restrict__ Bmat,
      float* __restrict__ Cout, int M, int N, int K)
{
    __shared__ float As[8 * 128];
    __shared__ float Bs[8 * 128];

    const int tid = threadIdx.x;
    const int bm = blockIdx.y * 128;
    const int bn = blockIdx.x * 128;
    const int lrow = tid >> 1;
    const int lk   = (tid & 1) * 4;
    const int tx = tid & 15;
    const int ty = tid >> 4;

    const float* A = (MODE == 0) ? Aext : ((MODE == 1) ? g_xproj : g_hs);

    float acc[8][8];
#pragma unroll
    for (int i = 0; i < 8; i++)
#pragma unroll
        for (int j = 0; j < 8; j++) acc[i][j] = 0.0f;

    for (int kt = 0; kt < K; kt += 8) {
        float4 av = *(const float4*)(A + (size_t)(bm + lrow) * K + kt + lk);
        if (MODE == 2) {
            float4 sv = *(const float4*)(g_siluz + (size_t)(bm + lrow) * K + kt + lk);
            av.x *= sv.x; av.y *= sv.y; av.z *= sv.z; av.w *= sv.w;
        }
        As[(lk + 0) * 128 + lrow] = av.x;
        As[(lk + 1) * 128 + lrow] = av.y;
        As[(lk + 2) * 128 + lrow] = av.z;
        As[(lk + 3) * 128 + lrow] = av.w;
        float4 bv = *(const float4*)(Bmat + (size_t)(bn + lrow) * K + kt + lk);
        Bs[(lk + 0) * 128 + lrow] = bv.x;
        Bs[(lk + 1) * 128 + lrow] = bv.y;
        Bs[(lk + 2) * 128 + lrow] = bv.z;
        Bs[(lk + 3) * 128 + lrow] = bv.w;
        __syncthreads();
#pragma unroll
        for (int kk = 0; kk < 8; kk++) {
            float af[8], bf[8];
            *(float4*)(af + 0) = *(const float4*)(As + kk * 128 + ty * 8 + 0);
            *(float4*)(af + 4) = *(const float4*)(As + kk * 128 + ty * 8 + 4);
            *(float4*)(bf + 0) = *(const float4*)(Bs + kk * 128 + tx * 8 + 0);
            *(float4*)(bf + 4) = *(const float4*)(Bs + kk * 128 + tx * 8 + 4);
#pragma unroll
            for (int i = 0; i < 8; i++)
#pragma unroll
                for (int j = 0; j < 8; j++)
                    acc[i][j] = fmaf(af[i], bf[j], acc[i][j]);
        }
        __syncthreads();
    }

#pragma unroll
    for (int i = 0; i < 8; i++) {
        const size_t m = (size_t)(bm + ty * 8 + i);
#pragma unroll
        for (int j = 0; j < 8; j++) {
            const int gn = bn + tx * 8 + j;
            float v = acc[i][j];
            if (MODE == 0) {
                if (gn < DDIM) g_xproj[m * DDIM + gn] = siluf(v);
                else           g_siluz[m * DDIM + (gn - DDIM)] = siluf(v);
            } else if (MODE == 1) {
                g_xw[m * DDIM + gn] = v;
            } else {
                Cout[m * DDIM + gn] = v;
            }
        }
    }
}

// ---------------- init: zero flags (every replay) ----------------
__global__ void init_kernel() {
    int i = blockIdx.x * blockDim.x + threadIdx.x;
    if (i < BATCH * CPB * 32) ((int*)g_flag)[i] = 0;
}

// ---------------- smem layout (float offsets) ----------------
#define WH_F    0                       // 64*512 = 32768
#define TAPE_F  (WH_F + SLICE*DDIM)     // 32*513 = 16416
#define HPRE_F  (TAPE_F + NSLOT*513)    // 512
#define HNEW_F  (HPRE_F + DDIM)         // 512
#define WVAL_F  (HNEW_F + DDIM)         // 512
#define SS_F    (WVAL_F + DDIM)         // 32  s_n = tape_old·hpre
#define WS_F    (SS_F + 32)             // 32
#define AS_F    (WS_F + 32)             // 32
#define BVS_F   (AS_F + 32)             // 32
#define PUB_F   (BVS_F + 32)            // 128
#define BH_F    (PUB_F + 128)           // 64
#define XWB_F   (BH_F + 64)             // 64
#define SCAN_SMEM_F (XWB_F + 64)

// ---------------- dual-memory scan (chain-shortened algebra) ----------------
__global__ void __launch_bounds__(SCAN_THREADS, 1)
scan_kernel(const float* __restrict__ W_h, const float* __restrict__ W_write,
            const float* __restrict__ b_h, float* __restrict__ dout)
{
    extern __shared__ float sm[];
    float* Wh_s   = sm + WH_F;
    float* tape_s = sm + TAPE_F;
    float* hpre_s = sm + HPRE_F;
    float* hnew_s = sm + HNEW_F;
    float* wval_s = sm + WVAL_F;
    float* s_s    = sm + SS_F;
    float* ws_s   = sm + WS_F;
    float* a_s    = sm + AS_F;
    float* bv_s   = sm + BVS_F;
    float* pub_s  = sm + PUB_F;
    float* bh_s   = sm + BH_F;
    float* xwb_s  = sm + XWB_F;

    const int tid  = threadIdx.x;
    const int wid  = tid >> 5;
    const int lane = tid & 31;
    const int b    = blockIdx.x / CPB;
    const int c    = blockIdx.x % CPB;
    const int dbase = c * SLICE;
    const float scale = 0.044194173824159216f;  // 1/sqrt(512)
    const unsigned F = 0xffffffffu;

    // ---- weight shards ----
    for (int i = tid; i < SLICE * DDIM / 4; i += SCAN_THREADS)
        ((float4*)Wh_s)[i] = ((const float4*)(W_h + (size_t)dbase * DDIM))[i];

    // W_write rows (dbase + wid*4 + 0..3) in registers
    float ww0[16], ww1[16], ww2[16], ww3[16];
    {
        const float* base = W_write + (size_t)(dbase + wid * 4) * DDIM + lane;
#pragma unroll
        for (int kk = 0; kk < 16; kk++) {
            ww0[kk] = base[kk * 32];
            ww1[kk] = base[DDIM + kk * 32];
            ww2[kk] = base[2 * DDIM + kk * 32];
            ww3[kk] = base[3 * DDIM + kk * 32];
        }
    }
    for (int i = tid; i < NSLOT * 513; i += SCAN_THREADS) tape_s[i] = 0.0f;
    wval_s[tid] = 0.0f;
    // full h_pre[0] = xw[0] + b_h  (work0 = 0)
    hpre_s[tid] = g_xw[((size_t)b * TSTEPS) * DDIM + tid] + b_h[tid];
    if (tid < SLICE) {
        bh_s[tid]  = b_h[dbase + tid];
        xwb_s[tid] = g_xw[((size_t)b * TSTEPS + 1) * DDIM + dbase + tid];
    }
    if (tid < NSLOT) bv_s[tid] = 0.0f;   // b[-1] = 0 -> no pending update at t=0
    __syncthreads();

    for (int t = 0; t < TSTEPS; t++) {
        const int par = t & 1;

        // ---- A (t>0): gather combined msg t; entmax(b[t-1]) on warp 0;
        //      own-slice copy; xw prefetch; g_hs store ----
        if (t > 0) {
            if (wid == 0) {
                bv_s[lane] = entmax15_warp(ws_s[lane] * scale, lane);   // b[t-1]
            } else if (wid >= 8) {
                int p = wid - 8;
                if (p != c) {
                    if (lane == 0) {
                        while (ld_acquire_gpu(&g_flag[b][p][0]) < t) {}
                    }
                    __syncwarp();
                    float4 v = __ldcg((const float4*)&g_ex[b][par][p][lane * 4]);
                    int j = lane * 4;
                    if (j < 64) *(float4*)&hpre_s[p * 64 + j]        = v;
                    else        *(float4*)&wval_s[p * 64 + (j - 64)] = v;
                }
            } else if (wid <= 4) {            // warps 1..4: copy own 128 floats
                int j = tid - 32;             // 0..127
                float v = pub_s[j];
                if (j < 64) hpre_s[dbase + j]        = v;
                else        wval_s[dbase + (j - 64)] = v;
            } else if (wid == 5) {            // prefetch xw[t+1] slice
                if (t + 1 < TSTEPS) {
                    xwb_s[lane]      = g_xw[((size_t)b * TSTEPS + t + 1) * DDIM + dbase + lane];
                    xwb_s[lane + 32] = g_xw[((size_t)b * TSTEPS + t + 1) * DDIM + dbase + lane + 32];
                }
            } else {                          // warps 6,7: store h_new[t-1]
                int j = tid - 192;            // 0..63
                g_hs[((size_t)b * TSTEPS + (t - 1)) * DDIM + dbase + j] = hnew_s[dbase + j];
            }
        }
        __syncthreads();

        // ---- B: s_n = tape_old[n]·hpre (2 rows/warp; NO update yet) ----
        {
            const int n0 = 2 * wid;
            const float* t0 = &tape_s[n0 * 513];
            const float* t1 = t0 + 513;
            float r0 = 0.f, r1 = 0.f;
#pragma unroll
            for (int kk = 0; kk < 16; kk++) {
                int d = lane + kk * 32;
                float hp = hpre_s[d];
                r0 = fmaf(t0[d], hp, r0);
                r1 = fmaf(t1[d], hp, r1);
            }
#pragma unroll
            for (int o = 16; o > 0; o >>= 1) {
                r0 += __shfl_xor_sync(F, r0, o);
                r1 += __shfl_xor_sync(F, r1, o);
            }
            if (lane == 0) { s_s[n0] = r0; s_s[n0 + 1] = r1; }
        }
        __syncthreads();

        // ---- C: warp 0: u = wval·hpre, r_n = s_n + b_n(u - s_n), entmax(a);
        //      warps 1-15: apply deferred tape update (t-1) in parallel ----
        if (wid == 0) {
            float u = 0.f;
#pragma unroll
            for (int kk = 0; kk < 16; kk++) {
                int d = lane + kk * 32;
                u = fmaf(wval_s[d], hpre_s[d], u);
            }
#pragma unroll
            for (int o = 16; o > 0; o >>= 1) u += __shfl_xor_sync(F, u, o);
            float bn = bv_s[lane];
            float sn = s_s[lane];
            float r  = fmaf(bn, u - sn, sn);   // (1-b)s + b·u
            a_s[lane] = entmax15_warp(r * scale, lane);
        } else if (t > 0) {
            for (int r = wid - 1; r < NSLOT; r += 15) {
                float bb = bv_s[r];
                float* tr = &tape_s[r * 513];
#pragma unroll
                for (int kk = 0; kk < 16; kk++) {
                    int d = lane + kk * 32;
                    float v = tr[d];
                    tr[d] = fmaf(bb, wval_s[d] - v, v);
                }
            }
        }
        __syncthreads();

        // ---- D: h_new[tid] = tanh(hpre + sum_n a_s[n]*tape[n][tid]) ----
        {
            float rd = 0.f;
#pragma unroll
            for (int n = 0; n < NSLOT; n++)
                rd = fmaf(a_s[n], tape_s[n * 513 + tid], rd);
            hnew_s[tid] = tanhf(hpre_s[tid] + rd);
        }
        __syncthreads();

        // ---- E: fused matvecs — W_h (4 rows, smem) + W_write (4 rows, regs) per warp ----
        {
            const int r0 = wid * 4;
            const bool doWh = (t + 1 < TSTEPS);
            const float* w0 = &Wh_s[(r0 + 0) * DDIM];
            const float* w1 = &Wh_s[(r0 + 1) * DDIM];
            const float* w2 = &Wh_s[(r0 + 2) * DDIM];
            const float* w3 = &Wh_s[(r0 + 3) * DDIM];
            float h0 = 0.f, h1 = 0.f, h2 = 0.f, h3 = 0.f;   // W_h accs
            float v0 = 0.f, v1 = 0.f, v2 = 0.f, v3 = 0.f;   // W_write accs
#pragma unroll
            for (int kk = 0; kk < 16; kk++) {
                int d = lane + kk * 32;
                float hv = hnew_s[d];
                v0 = fmaf(ww0[kk], hv, v0);
                v1 = fmaf(ww1[kk], hv, v1);
                v2 = fmaf(ww2[kk], hv, v2);
                v3 = fmaf(ww3[kk], hv, v3);
                if (doWh) {
                    h0 = fmaf(w0[d], hv, h0);
                    h1 = fmaf(w1[d], hv, h1);
                    h2 = fmaf(w2[d], hv, h2);
                    h3 = fmaf(w3[d], hv, h3);
                }
            }
#pragma unroll
            for (int o = 16; o > 0; o >>= 1) {
                v0 += __shfl_xor_sync(F, v0, o);
                v1 += __shfl_xor_sync(F, v1, o);
                v2 += __shfl_xor_sync(F, v2, o);
                v3 += __shfl_xor_sync(F, v3, o);
                h0 += __shfl_xor_sync(F, h0, o);
                h1 += __shfl_xor_sync(F, h1, o);
                h2 += __shfl_xor_sync(F, h2, o);
                h3 += __shfl_xor_sync(F, h3, o);
            }
            if (lane == 0) {
                pub_s[64 + r0 + 0] = v0;
                pub_s[64 + r0 + 1] = v1;
                pub_s[64 + r0 + 2] = v2;
                pub_s[64 + r0 + 3] = v3;
                if (doWh) {
                    pub_s[r0 + 0] = h0 + xwb_s[r0 + 0] + bh_s[r0 + 0];
                    pub_s[r0 + 1] = h1 + xwb_s[r0 + 1] + bh_s[r0 + 1];
                    pub_s[r0 + 2] = h2 + xwb_s[r0 + 2] + bh_s[r0 + 2];
                    pub_s[r0 + 3] = h3 + xwb_s[r0 + 3] + bh_s[r0 + 3];
                }
            }
        }
        __syncthreads();

        // ---- F: publish msg t+1 (warp c+8, no threadfence — release orders);
        //      all warps: w-scores (tape state t-1-final) ----
        if (wid == c + 8 && t + 1 < TSTEPS) {
            float4 v = ((const float4*)pub_s)[lane];
            __stcg((float4*)&g_ex[b][(t + 1) & 1][c][lane * 4], v);
            __syncwarp();
            if (lane == 0) st_release_gpu(&g_flag[b][c][0], t + 1);
        }
        {
            const int n0 = 2 * wid;
            const float* t0 = &tape_s[n0 * 513];
            const float* t1 = t0 + 513;
            float s0 = 0.f, s1 = 0.f;
#pragma unroll
            for (int kk = 0; kk < 16; kk++) {
                int d = lane + kk * 32;
                float hv = hnew_s[d];
                s0 = fmaf(t0[d], hv, s0);
                s1 = fmaf(t1[d], hv, s1);
            }
#pragma unroll
            for (int o = 16; o > 0; o >>= 1) {
                s0 += __shfl_xor_sync(F, s0, o);
                s1 += __shfl_xor_sync(F, s1, o);
            }
            if (lane == 0) { ws_s[n0] = s0; ws_s[n0 + 1] = s1; }
        }
        __syncthreads();
    }

    // ---- post-loop: entmax(b[T-1]), final tape update (own cols), outputs ----
    if (wid == 0) bv_s[lane] = entmax15_warp(ws_s[lane] * scale, lane);
    __syncthreads();

    const size_t TAPE_OFF = (size_t)BATCH * TSTEPS * DDIM;
    const size_t WORK_OFF = TAPE_OFF + (size_t)BATCH * NSLOT * DDIM;
    {
        const int n0 = 2 * wid;
        float bb0 = bv_s[n0];
        float bb1 = bv_s[n0 + 1];
#pragma unroll
        for (int h = 0; h < 2; h++) {
            int j = lane + h * 32;           // 0..63 own-column index
            int d = dbase + j;
            float wv = pub_s[64 + j];        // wval[T-1] own slice (local)
            float v0 = tape_s[n0 * 513 + d];
            float v1 = tape_s[(n0 + 1) * 513 + d];
            v0 = fmaf(bb0, wv - v0, v0);
            v1 = fmaf(bb1, wv - v1, v1);
            dout[TAPE_OFF + ((size_t)b * NSLOT + n0) * DDIM + d]     = v0;
            dout[TAPE_OFF + ((size_t)b * NSLOT + n0 + 1) * DDIM + d] = v1;
        }
    }
    if (tid < SLICE) {
        g_hs[((size_t)b * TSTEPS + TSTEPS - 1) * DDIM + dbase + tid] = hnew_s[dbase + tid];
        dout[WORK_OFF + (size_t)b * DDIM + dbase + tid] = hnew_s[dbase + tid];
    }
}

// ---------------- launcher ----------------
extern "C" void kernel_launch(void* const* d_in, const int* in_sizes, int n_in,
                              void* d_out, int out_size)
{
    const float* x       = (const float*)d_in[0];
    const float* W_in    = (const float*)d_in[1];
    const float* W_out   = (const float*)d_in[2];
    const float* W_h     = (const float*)d_in[3];
    const float* W_x     = (const float*)d_in[4];
    const float* b_h     = (const float*)d_in[5];
    const float* W_write = (const float*)d_in[6];
    float* out = (float*)d_out;

    const int scan_smem = SCAN_SMEM_F * (int)sizeof(float);
    cudaFuncSetAttribute(scan_kernel, cudaFuncAttributeMaxDynamicSharedMemorySize, scan_smem);

    dim3 blk(256);
    sgemm<0><<<dim3(1024 / 128, MROWS / 128), blk>>>(x, W_in, nullptr, MROWS, 1024, DDIM);
    sgemm<1><<<dim3(DDIM / 128, MROWS / 128), blk>>>(nullptr, W_x, nullptr, MROWS, DDIM, DDIM);
    init_kernel<<<8, 256>>>();
    scan_kernel<<<BATCH * CPB, SCAN_THREADS, scan_smem>>>(W_h, W_write, b_h, out);
    sgemm<2><<<dim3(DDIM / 128, MROWS / 128), blk>>>(nullptr, W_out, out, MROWS, DDIM, DDIM);
}

// round 13
// speedup vs baseline: 1.9617x; 1.1163x over previous
#include <cuda_runtime.h>
#include <math.h>
#include <stdint.h>

// ---------------- problem constants ----------------
#define DDIM 512
#define TSTEPS 1024
#define BATCH 8
#define NSLOT 32
#define CPB 8             // CTAs per batch (plain grid)
#define SLICE 64          // d-slice per CTA
#define MROWS (BATCH*TSTEPS)
#define SCAN_THREADS 512
#define MSGF 176          // message floats (161 used, padded to 44 float4)

// ---------------- static device scratch ----------------
__device__ float g_xproj[(size_t)MROWS * DDIM];
__device__ float g_siluz[(size_t)MROWS * DDIM];
__device__ float g_xw   [(size_t)MROWS * DDIM];
__device__ float g_hs   [(size_t)MROWS * DDIM];

// combined exchange per CTA per step:
// [0:64]=h_pre[t] slice, [64:128]=w_val[t-1] slice,
// [128:160]=s_n partials (tape[t-2]·hpre[t] over own cols), [160]=u partial
__device__ __align__(16) float g_ex[BATCH][2][CPB][MSGF];
__device__ int   g_flag[BATCH][CPB][32];   // use [b][c][0]; 128B padded

__device__ __forceinline__ float siluf(float v) { return v / (1.0f + __expf(-v)); }

__device__ __forceinline__ int ld_acquire_gpu(const int* p) {
    int v;
    asm volatile("ld.acquire.gpu.global.s32 %0, [%1];" : "=r"(v) : "l"(p) : "memory");
    return v;
}
__device__ __forceinline__ void st_release_gpu(int* p, int v) {
    asm volatile("st.release.gpu.global.s32 [%0], %1;" :: "l"(p), "r"(v) : "memory");
}

// ---------------- exact 1.5-entmax over 32 values, one per lane (proven) ----------------
__device__ __forceinline__ float entmax15_warp(float z, int lane) {
    const unsigned F = 0xffffffffu;
    float x0 = 0.5f * z;
    int rank = 0;
#pragma unroll
    for (int j = 0; j < 32; j++) {
        float xj = __shfl_sync(F, x0, j);
        rank += (xj > x0 || (xj == x0 && j < lane)) ? 1 : 0;
    }
    float m = x0;
#pragma unroll
    for (int o = 16; o > 0; o >>= 1) m = fmaxf(m, __shfl_xor_sync(F, m, o));
    float x = x0 - m;
    float s = 0.f, s2 = 0.f, zsv = 0.f;
#pragma unroll
    for (int j = 0; j < 32; j++) {
        float xj = __shfl_sync(F, x, j);
        int   rj = __shfl_sync(F, rank, j);
        if (rj <= lane) { s += xj; s2 += xj * xj; }
        if (rj == lane) zsv = xj;
    }
    float k1     = (float)(lane + 1);
    float mean   = s / k1;
    float meansq = s2 / k1;
    float ss     = k1 * (meansq - mean * mean);
    float delta  = (1.0f - ss) / k1;
    float tau    = mean - sqrtf(fmaxf(delta, 0.0f));
    unsigned bal = __ballot_sync(F, tau <= zsv);
    int support  = __popc(bal) - 1;
    float tau_star = __shfl_sync(F, tau, support);
    float p = fmaxf(x - tau_star, 0.0f);
    return p * p;
}

// ---------------- SGEMM: C[M,N] = A[M,K] @ B[N,K]^T (proven) ----------------
template <int MODE>
__global__ void __launch_bounds__(256)
sgemm(const float* __restrict__ Aext, const float* __restrict__ Bmat,
      float* __restrict__ Cout, int M, int N, int K)
{
    __shared__ float As[8 * 128];
    __shared__ float Bs[8 * 128];

    const int tid = threadIdx.x;
    const int bm = blockIdx.y * 128;
    const int bn = blockIdx.x * 128;
    const int lrow = tid >> 1;
    const int lk   = (tid & 1) * 4;
    const int tx = tid & 15;
    const int ty = tid >> 4;

    const float* A = (MODE == 0) ? Aext : ((MODE == 1) ? g_xproj : g_hs);

    float acc[8][8];
#pragma unroll
    for (int i = 0; i < 8; i++)
#pragma unroll
        for (int j = 0; j < 8; j++) acc[i][j] = 0.0f;

    for (int kt = 0; kt < K; kt += 8) {
        float4 av = *(const float4*)(A + (size_t)(bm + lrow) * K + kt + lk);
        if (MODE == 2) {
            float4 sv = *(const float4*)(g_siluz + (size_t)(bm + lrow) * K + kt + lk);
            av.x *= sv.x; av.y *= sv.y; av.z *= sv.z; av.w *= sv.w;
        }
        As[(lk + 0) * 128 + lrow] = av.x;
        As[(lk + 1) * 128 + lrow] = av.y;
        As[(lk + 2) * 128 + lrow] = av.z;
        As[(lk + 3) * 128 + lrow] = av.w;
        float4 bv = *(const float4*)(Bmat + (size_t)(bn + lrow) * K + kt + lk);
        Bs[(lk + 0) * 128 + lrow] = bv.x;
        Bs[(lk + 1) * 128 + lrow] = bv.y;
        Bs[(lk + 2) * 128 + lrow] = bv.z;
        Bs[(lk + 3) * 128 + lrow] = bv.w;
        __syncthreads();
#pragma unroll
        for (int kk = 0; kk < 8; kk++) {
            float af[8], bf[8];
            *(float4*)(af + 0) = *(const float4*)(As + kk * 128 + ty * 8 + 0);
            *(float4*)(af + 4) = *(const float4*)(As + kk * 128 + ty * 8 + 4);
            *(float4*)(bf + 0) = *(const float4*)(Bs + kk * 128 + tx * 8 + 0);
            *(float4*)(bf + 4) = *(const float4*)(Bs + kk * 128 + tx * 8 + 4);
#pragma unroll
            for (int i = 0; i < 8; i++)
#pragma unroll
                for (int j = 0; j < 8; j++)
                    acc[i][j] = fmaf(af[i], bf[j], acc[i][j]);
        }
        __syncthreads();
    }

#pragma unroll
    for (int i = 0; i < 8; i++) {
        const size_t m = (size_t)(bm + ty * 8 + i);
#pragma unroll
        for (int j = 0; j < 8; j++) {
            const int gn = bn + tx * 8 + j;
            float v = acc[i][j];
            if (MODE == 0) {
                if (gn < DDIM) g_xproj[m * DDIM + gn] = siluf(v);
                else           g_siluz[m * DDIM + (gn - DDIM)] = siluf(v);
            } else if (MODE == 1) {
                g_xw[m * DDIM + gn] = v;
            } else {
                Cout[m * DDIM + gn] = v;
            }
        }
    }
}

// ---------------- init: zero flags (every replay) ----------------
__global__ void init_kernel() {
    int i = blockIdx.x * blockDim.x + threadIdx.x;
    if (i < BATCH * CPB * 32) ((int*)g_flag)[i] = 0;
}

// ---------------- smem layout (float offsets) ----------------
#define WH_F    0                       // 64*512 = 32768
#define TAPE_F  (WH_F + SLICE*DDIM)     // 32*513 = 16416
#define HPRE_F  (TAPE_F + NSLOT*513)    // 512
#define HNEW_F  (HPRE_F + DDIM)         // 512
#define WVAL_F  (HNEW_F + DDIM)         // 512
#define WS_F    (WVAL_F + DDIM)         // 32
#define AS_F    (WS_F + 32)             // 32
#define BVS_F   (AS_F + 32)             // 32
#define SP_F    (BVS_F + 32)            // CPB*32 = 256 s-partials
#define UP_F    (SP_F + CPB*32)         // CPB = 8 u-partials
#define PUB_F   (UP_F + 8)              // 176
#define BH_F    (PUB_F + MSGF)          // 64
#define XWB_F   (BH_F + 64)             // 64
#define SCAN_SMEM_F (XWB_F + 64)

// ---------------- dual-memory scan (shipped score partials) ----------------
__global__ void __launch_bounds__(SCAN_THREADS, 1)
scan_kernel(const float* __restrict__ W_h, const float* __restrict__ W_write,
            const float* __restrict__ b_h, float* __restrict__ dout)
{
    extern __shared__ float sm[];
    float* Wh_s   = sm + WH_F;
    float* tape_s = sm + TAPE_F;
    float* hpre_s = sm + HPRE_F;
    float* hnew_s = sm + HNEW_F;
    float* wval_s = sm + WVAL_F;
    float* ws_s   = sm + WS_F;
    float* a_s    = sm + AS_F;
    float* bv_s   = sm + BVS_F;
    float* sp_s   = sm + SP_F;
    float* up_s   = sm + UP_F;
    float* pub_s  = sm + PUB_F;
    float* bh_s   = sm + BH_F;
    float* xwb_s  = sm + XWB_F;

    const int tid  = threadIdx.x;
    const int wid  = tid >> 5;
    const int lane = tid & 31;
    const int b    = blockIdx.x / CPB;
    const int c    = blockIdx.x % CPB;
    const int dbase = c * SLICE;
    const float scale = 0.044194173824159216f;  // 1/sqrt(512)
    const unsigned F = 0xffffffffu;

    // ---- weight shards ----
    for (int i = tid; i < SLICE * DDIM / 4; i += SCAN_THREADS)
        ((float4*)Wh_s)[i] = ((const float4*)(W_h + (size_t)dbase * DDIM))[i];

    // W_write rows (dbase + wid*4 + 0..3) in registers
    float ww0[16], ww1[16], ww2[16], ww3[16];
    {
        const float* base = W_write + (size_t)(dbase + wid * 4) * DDIM + lane;
#pragma unroll
        for (int kk = 0; kk < 16; kk++) {
            ww0[kk] = base[kk * 32];
            ww1[kk] = base[DDIM + kk * 32];
            ww2[kk] = base[2 * DDIM + kk * 32];
            ww3[kk] = base[3 * DDIM + kk * 32];
        }
    }
    for (int i = tid; i < NSLOT * 513; i += SCAN_THREADS) tape_s[i] = 0.0f;
    wval_s[tid] = 0.0f;
    // full h_pre[0] = xw[0] + b_h  (work0 = 0)
    hpre_s[tid] = g_xw[((size_t)b * TSTEPS) * DDIM + tid] + b_h[tid];
    if (tid < SLICE) {
        bh_s[tid]  = b_h[dbase + tid];
        xwb_s[tid] = g_xw[((size_t)b * TSTEPS + 1) * DDIM + dbase + tid];
    }
    if (tid < NSLOT) bv_s[tid] = 0.0f;           // b[-1] = 0
    if (tid < CPB * 32) sp_s[tid] = 0.0f;        // S at t=0 -> 0 (tape[-1]=0)
    if (tid < CPB) up_s[tid] = 0.0f;
    __syncthreads();

    for (int t = 0; t < TSTEPS; t++) {
        const int par = t & 1;

        // ---- A (t>0): entmax(b[t-1]) on warp 0; gather msg t (warps 8-15);
        //      own-slice copies; xw prefetch; g_hs store ----
        if (t > 0) {
            if (wid == 0) {
                bv_s[lane] = entmax15_warp(ws_s[lane] * scale, lane);   // b[t-1]
            } else if (wid >= 8) {
                int p = wid - 8;
                if (p != c) {
                    if (lane == 0) {
                        while (ld_acquire_gpu(&g_flag[b][p][0]) < t) {}
                    }
                    __syncwarp();
                    float4 v = __ldcg((const float4*)&g_ex[b][par][p][lane * 4]);
                    int j = lane * 4;
                    if (j < 64) *(float4*)&hpre_s[p * 64 + j]        = v;
                    else        *(float4*)&wval_s[p * 64 + (j - 64)] = v;
                    if (lane < 9) {
                        float4 v2 = __ldcg((const float4*)&g_ex[b][par][p][128 + lane * 4]);
                        if (lane < 8) *(float4*)&sp_s[p * 32 + lane * 4] = v2;
                        else          up_s[p] = v2.x;
                    }
                }
            } else if (wid <= 4) {            // warps 1..4: copy own 128 floats
                int j = tid - 32;             // 0..127
                float v = pub_s[j];
                if (j < 64) hpre_s[dbase + j]        = v;
                else        wval_s[dbase + (j - 64)] = v;
            } else if (wid == 5) {            // prefetch xw[t+1] slice
                if (t + 1 < TSTEPS) {
                    xwb_s[lane]      = g_xw[((size_t)b * TSTEPS + t + 1) * DDIM + dbase + lane];
                    xwb_s[lane + 32] = g_xw[((size_t)b * TSTEPS + t + 1) * DDIM + dbase + lane + 32];
                }
            } else {                          // warps 6,7: store h_new[t-1]
                int j = tid - 192;            // 0..63
                g_hs[((size_t)b * TSTEPS + (t - 1)) * DDIM + dbase + j] = hnew_s[dbase + j];
            }
        }
        __syncthreads();

        // ---- C: warp 0: combine shipped partials, r_n = (1-b)S + bU, entmax(a);
        //      warps 1-15: apply deferred tape update (t-1) in parallel ----
        if (wid == 0) {
            float S = 0.f, U = 0.f;
#pragma unroll
            for (int p = 0; p < CPB; p++) {
                S += sp_s[p * 32 + lane];
                U += up_s[p];
            }
            float bn = bv_s[lane];
            float r  = fmaf(bn, U - S, S);
            a_s[lane] = entmax15_warp(r * scale, lane);
        } else if (t > 0) {
            for (int r = wid - 1; r < NSLOT; r += 15) {
                float bb = bv_s[r];
                float* tr = &tape_s[r * 513];
#pragma unroll
                for (int kk = 0; kk < 16; kk++) {
                    int d = lane + kk * 32;
                    float v = tr[d];
                    tr[d] = fmaf(bb, wval_s[d] - v, v);
                }
            }
        }
        __syncthreads();

        // ---- D: h_new[tid] = tanh(hpre + sum_n a_s[n]*tape[n][tid]) ----
        {
            float rd = 0.f;
#pragma unroll
            for (int n = 0; n < NSLOT; n++)
                rd = fmaf(a_s[n], tape_s[n * 513 + tid], rd);
            hnew_s[tid] = tanhf(hpre_s[tid] + rd);
        }
        __syncthreads();

        // ---- E: fused matvecs — W_h (4 rows, smem) + W_write (4 rows, regs) per warp ----
        {
            const int r0 = wid * 4;
            const bool doWh = (t + 1 < TSTEPS);
            const float* w0 = &Wh_s[(r0 + 0) * DDIM];
            const float* w1 = &Wh_s[(r0 + 1) * DDIM];
            const float* w2 = &Wh_s[(r0 + 2) * DDIM];
            const float* w3 = &Wh_s[(r0 + 3) * DDIM];
            float h0 = 0.f, h1 = 0.f, h2 = 0.f, h3 = 0.f;   // W_h accs
            float v0 = 0.f, v1 = 0.f, v2 = 0.f, v3 = 0.f;   // W_write accs
#pragma unroll
            for (int kk = 0; kk < 16; kk++) {
                int d = lane + kk * 32;
                float hv = hnew_s[d];
                v0 = fmaf(ww0[kk], hv, v0);
                v1 = fmaf(ww1[kk], hv, v1);
                v2 = fmaf(ww2[kk], hv, v2);
                v3 = fmaf(ww3[kk], hv, v3);
                if (doWh) {
                    h0 = fmaf(w0[d], hv, h0);
                    h1 = fmaf(w1[d], hv, h1);
                    h2 = fmaf(w2[d], hv, h2);
                    h3 = fmaf(w3[d], hv, h3);
                }
            }
#pragma unroll
            for (int o = 16; o > 0; o >>= 1) {
                v0 += __shfl_xor_sync(F, v0, o);
                v1 += __shfl_xor_sync(F, v1, o);
                v2 += __shfl_xor_sync(F, v2, o);
                v3 += __shfl_xor_sync(F, v3, o);
                h0 += __shfl_xor_sync(F, h0, o);
                h1 += __shfl_xor_sync(F, h1, o);
                h2 += __shfl_xor_sync(F, h2, o);
                h3 += __shfl_xor_sync(F, h3, o);
            }
            if (lane == 0) {
                pub_s[64 + r0 + 0] = v0;
                pub_s[64 + r0 + 1] = v1;
                pub_s[64 + r0 + 2] = v2;
                pub_s[64 + r0 + 3] = v3;
                if (doWh) {
                    pub_s[r0 + 0] = h0 + xwb_s[r0 + 0] + bh_s[r0 + 0];
                    pub_s[r0 + 1] = h1 + xwb_s[r0 + 1] + bh_s[r0 + 1];
                    pub_s[r0 + 2] = h2 + xwb_s[r0 + 2] + bh_s[r0 + 2];
                    pub_s[r0 + 3] = h3 + xwb_s[r0 + 3] + bh_s[r0 + 3];
                }
            }
        }
        __syncthreads();

        // ---- F1 (t+1<T): score partials for msg t+1 (tape[t-1], own 64 cols);
        //      warp 0 additionally u = wval·hpre over own cols ----
        if (t + 1 < TSTEPS) {
            const int n0 = 2 * wid;
            const float* t0 = &tape_s[n0 * 513 + dbase];
            const float* t1 = t0 + 513;
            float hp0 = pub_s[lane];
            float hp1 = pub_s[lane + 32];
            float s0 = t0[lane] * hp0 + t0[lane + 32] * hp1;
            float s1 = t1[lane] * hp0 + t1[lane + 32] * hp1;
            float uu = 0.f;
            if (wid == 0)
                uu = pub_s[64 + lane] * hp0 + pub_s[96 + lane] * hp1;
#pragma unroll
            for (int o = 16; o > 0; o >>= 1) {
                s0 += __shfl_xor_sync(F, s0, o);
                s1 += __shfl_xor_sync(F, s1, o);
                uu += __shfl_xor_sync(F, uu, o);
            }
            if (lane == 0) {
                pub_s[128 + n0]     = s0;
                pub_s[128 + n0 + 1] = s1;
                sp_s[c * 32 + n0]     = s0;
                sp_s[c * 32 + n0 + 1] = s1;
                if (wid == 0) { pub_s[160] = uu; up_s[c] = uu; }
            }
        }
        __syncthreads();

        // ---- F2: publish msg t+1 (warp c+8); all warps: w-scores ----
        if (wid == c + 8 && t + 1 < TSTEPS) {
            float4 v = ((const float4*)pub_s)[lane];
            __stcg((float4*)&g_ex[b][(t + 1) & 1][c][lane * 4], v);
            if (lane < 9) {
                float4 v2 = ((const float4*)pub_s)[32 + lane];
                __stcg((float4*)&g_ex[b][(t + 1) & 1][c][128 + lane * 4], v2);
            }
            __syncwarp();
            if (lane == 0) st_release_gpu(&g_flag[b][c][0], t + 1);
        }
        {
            const int n0 = 2 * wid;
            const float* t0 = &tape_s[n0 * 513];
            const float* t1 = t0 + 513;
            float s0 = 0.f, s1 = 0.f;
#pragma unroll
            for (int kk = 0; kk < 16; kk++) {
                int d = lane + kk * 32;
                float hv = hnew_s[d];
                s0 = fmaf(t0[d], hv, s0);
                s1 = fmaf(t1[d], hv, s1);
            }
#pragma unroll
            for (int o = 16; o > 0; o >>= 1) {
                s0 += __shfl_xor_sync(F, s0, o);
                s1 += __shfl_xor_sync(F, s1, o);
            }
            if (lane == 0) { ws_s[n0] = s0; ws_s[n0 + 1] = s1; }
        }
        __syncthreads();
    }

    // ---- post-loop: entmax(b[T-1]), final tape update (own cols), outputs ----
    if (wid == 0) bv_s[lane] = entmax15_warp(ws_s[lane] * scale, lane);
    __syncthreads();

    const size_t TAPE_OFF = (size_t)BATCH * TSTEPS * DDIM;
    const size_t WORK_OFF = TAPE_OFF + (size_t)BATCH * NSLOT * DDIM;
    {
        const int n0 = 2 * wid;
        float bb0 = bv_s[n0];
        float bb1 = bv_s[n0 + 1];
#pragma unroll
        for (int h = 0; h < 2; h++) {
            int j = lane + h * 32;           // 0..63 own-column index
            int d = dbase + j;
            float wv = pub_s[64 + j];        // wval[T-1] own slice (local)
            float v0 = tape_s[n0 * 513 + d];
            float v1 = tape_s[(n0 + 1) * 513 + d];
            v0 = fmaf(bb0, wv - v0, v0);
            v1 = fmaf(bb1, wv - v1, v1);
            dout[TAPE_OFF + ((size_t)b * NSLOT + n0) * DDIM + d]     = v0;
            dout[TAPE_OFF + ((size_t)b * NSLOT + n0 + 1) * DDIM + d] = v1;
        }
    }
    if (tid < SLICE) {
        g_hs[((size_t)b * TSTEPS + TSTEPS - 1) * DDIM + dbase + tid] = hnew_s[dbase + tid];
        dout[WORK_OFF + (size_t)b * DDIM + dbase + tid] = hnew_s[dbase + tid];
    }
}

// ---------------- launcher ----------------
extern "C" void kernel_launch(void* const* d_in, const int* in_sizes, int n_in,
                              void* d_out, int out_size)
{
    const float* x       = (const float*)d_in[0];
    const float* W_in    = (const float*)d_in[1];
    const float* W_out   = (const float*)d_in[2];
    const float* W_h     = (const float*)d_in[3];
    const float* W_x     = (const float*)d_in[4];
    const float* b_h     = (const float*)d_in[5];
    const float* W_write = (const float*)d_in[6];
    float* out = (float*)d_out;

    const int scan_smem = SCAN_SMEM_F * (int)sizeof(float);
    cudaFuncSetAttribute(scan_kernel, cudaFuncAttributeMaxDynamicSharedMemorySize, scan_smem);

    dim3 blk(256);
    sgemm<0><<<dim3(1024 / 128, MROWS / 128), blk>>>(x, W_in, nullptr, MROWS, 1024, DDIM);
    sgemm<1><<<dim3(DDIM / 128, MROWS / 128), blk>>>(nullptr, W_x, nullptr, MROWS, DDIM, DDIM);
    init_kernel<<<8, 256>>>();
    scan_kernel<<<BATCH * CPB, SCAN_THREADS, scan_smem>>>(W_h, W_write, b_h, out);
    sgemm<2><<<dim3(DDIM / 128, MROWS / 128), blk>>>(nullptr, W_out, out, MROWS, DDIM, DDIM);
}